// round 6
// baseline (speedup 1.0000x reference)
#include <cuda_runtime.h>
#include <cstdint>

// Problem constants
#define M_SUB   8
#define N_E     1024
#define E_DIM   64
#define BS_     16
#define CC_     512
#define HW_     1024
#define NPOS    16384            // BS_*HW_

// Output layout (float32)
#define OFF_ZVQ  0
#define OFF_LOSS 8388608
#define OFF_IDX  8388609
#define OFF_BIN  8519681

// Scratch (device globals; no allocation allowed)
__device__ float  g_esq[M_SUB * N_E];
__device__ float  g_cbt[M_SUB * E_DIM * N_E];   // transposed codebooks [m][k][code]
__device__ double g_part[1024];

// ---------------- f32x2 packed FMA helpers -----------------------------------
__device__ __forceinline__ void upk2(unsigned long long v, float& lo, float& hi) {
    asm("mov.b64 {%0, %1}, %2;" : "=f"(lo), "=f"(hi) : "l"(v));
}
__device__ __forceinline__ unsigned long long fma2(unsigned long long a,
                                                   unsigned long long b,
                                                   unsigned long long c) {
    unsigned long long d;
    asm("fma.rn.f32x2 %0, %1, %2, %3;" : "=l"(d) : "l"(a), "l"(b), "l"(c));
    return d;
}

// ---------------- K0: zero bins -----------------------------------------------
__global__ void pq_init_kernel(float* __restrict__ outBins) {
    int t = threadIdx.x;
    if (t < N_E) outBins[t] = 0.0f;
}

// ---------------- K_esq: per-code squared norms (mul then sequential add) -----
__global__ void pq_esq_kernel(const float* __restrict__ cbk) {
    int t = blockIdx.x * blockDim.x + threadIdx.x;   // 0..8191
    if (t >= M_SUB * N_E) return;
    const float* p = cbk + (size_t)t * E_DIM;
    float s = 0.0f;
    #pragma unroll
    for (int d = 0; d < E_DIM; d++) {
        float v = p[d];
        s = __fadd_rn(s, __fmul_rn(v, v));
    }
    g_esq[t] = s;
}

// ---------------- K_tr: transpose codebooks to k-major ------------------------
// grid = 64 blocks (8 m x 8 code-tiles of 128), 256 threads
__global__ void pq_tr_kernel(const float* __restrict__ cbk) {
    __shared__ float st[64 * 128];
    int m  = blockIdx.x >> 3;
    int ct = (blockIdx.x & 7) * 128;
    int tid = threadIdx.x;
    int code = tid >> 1;             // 0..127
    int kh = (tid & 1) * 32;         // 0 or 32
    const float* src = cbk + ((size_t)(m * N_E) + ct + code) * E_DIM + kh;
    #pragma unroll
    for (int q = 0; q < 8; q++) {
        float4 v = *(const float4*)(src + q * 4);
        st[(kh + q * 4 + 0) * 128 + code] = v.x;
        st[(kh + q * 4 + 1) * 128 + code] = v.y;
        st[(kh + q * 4 + 2) * 128 + code] = v.z;
        st[(kh + q * 4 + 3) * 128 + code] = v.w;
    }
    __syncthreads();
    float* dst = g_cbt + (size_t)m * E_DIM * N_E + ct;
    #pragma unroll
    for (int it = 0; it < 8; it++) {
        int i = tid + it * 256;
        int k = i >> 5, c4 = (i & 31) * 4;
        *(float4*)(dst + (size_t)k * N_E + c4) = *(const float4*)(st + k * 128 + c4);
    }
}

// ---------------- K1: distances + argmin + fused z_vq/loss --------------------
// Block 256 threads. Tile: 128 rows x 1024 codes (8 chunks of 128).
// grid = (128 row-tiles, 8 sub-codebooks)
#define TN 128

__global__ void __launch_bounds__(256, 2)
pq_dist_kernel(const float* __restrict__ z,
               const float* __restrict__ cbk,
               float* __restrict__ outZvq,
               float* __restrict__ outIdx,
               float* __restrict__ outBins)
{
    extern __shared__ float sm[];
    float* szt  = sm;                        // 64*256 = 16384 (z tile, duplicated pairs)
    float* scb  = sm + 16384;                // 64*128 = 8192 (codebook chunk, k-major)
    float* sesq = scb + 8192;                // 1024
    float* szsq = sesq + 1024;               // 128
    int*   swin = (int*)(szsq + 128);        // 128
    // total 25856 floats = 103424 B

    __shared__ double swarp[8];

    const int m  = blockIdx.y;
    const int n0 = blockIdx.x * TN;
    const int b  = n0 >> 10;
    const int p0 = n0 & 1023;
    const int tid = threadIdx.x;
    const int tx = tid & 15, ty = tid >> 4;

    // Load z tile (channels [m*64, m*64+64), positions [p0, p0+128)), duplicated:
    // szt[k][2*j] = szt[k][2*j+1] = z[k][j]
    const float* zbase = z + ((size_t)(b * CC_ + m * E_DIM) * HW_) + p0;
    #pragma unroll
    for (int it = 0; it < 8; it++) {
        int i = tid + it * 256;
        int d = i >> 5, j4 = (i & 31) * 4;
        float4 v = *(const float4*)(zbase + (size_t)d * HW_ + j4);
        float* dst = szt + d * 256 + 2 * j4;
        *(float4*)(dst)     = make_float4(v.x, v.x, v.y, v.y);
        *(float4*)(dst + 4) = make_float4(v.z, v.z, v.w, v.w);
    }
    #pragma unroll
    for (int it = 0; it < 4; it++)
        sesq[tid + it * 256] = g_esq[m * N_E + tid + it * 256];
    __syncthreads();

    // per-row ||z||^2: square rounded, then sequential add
    if (tid < TN) {
        float s = 0.0f;
        #pragma unroll
        for (int k = 0; k < E_DIM; k++) {
            float v = szt[k * 256 + 2 * tid];
            s = __fadd_rn(s, __fmul_rn(v, v));
        }
        szsq[tid] = s;
    }
    __syncthreads();

    const int r0 = ty * 8;       // thread's 8 rows
    const int c0 = tx * 4;       // thread's codes: {c0..c0+3, 64+c0..64+c0+3} per chunk
    float zs[8];
    #pragma unroll
    for (int q = 0; q < 8; q++) zs[q] = szsq[r0 + q];

    const float INFF = __int_as_float(0x7f800000);
    float bd[8]; int bi[8];
    #pragma unroll
    for (int q = 0; q < 8; q++) { bd[q] = INFF; bi[q] = 0; }

    const float* ctb = g_cbt + (size_t)m * (E_DIM * N_E);

    for (int ch = 0; ch < 8; ch++) {
        __syncthreads();
        // fill codebook chunk (already k-major in gmem): 2048 float4
        #pragma unroll
        for (int it = 0; it < 8; it++) {
            int i = tid + it * 256;
            int k = i >> 5, c4 = (i & 31) * 4;
            float4 v = *(const float4*)(ctb + (size_t)k * N_E + ch * 128 + c4);
            *(float4*)(scb + k * 128 + c4) = v;
        }
        __syncthreads();

        unsigned long long acc[8][4];
        #pragma unroll
        for (int r = 0; r < 8; r++)
            #pragma unroll
            for (int j = 0; j < 4; j++) acc[r][j] = 0ull;

        #pragma unroll 4
        for (int k = 0; k < E_DIM; k++) {
            const float* zr = szt + k * 256 + 2 * r0;
            ulonglong2 za = *(const ulonglong2*)(zr);        // rows r0,r0+1 dup
            ulonglong2 zb = *(const ulonglong2*)(zr + 4);    // r0+2,r0+3
            ulonglong2 zc = *(const ulonglong2*)(zr + 8);
            ulonglong2 zd = *(const ulonglong2*)(zr + 12);
            const float* cr = scb + k * 128 + c0;
            ulonglong2 ca = *(const ulonglong2*)(cr);        // codes (c0,c0+1),(c0+2,c0+3)
            ulonglong2 cb = *(const ulonglong2*)(cr + 64);   // codes 64+c0 ...
            unsigned long long zp[8] = {za.x, za.y, zb.x, zb.y, zc.x, zc.y, zd.x, zd.y};
            unsigned long long cp[4] = {ca.x, ca.y, cb.x, cb.y};
            #pragma unroll
            for (int r = 0; r < 8; r++)
                #pragma unroll
                for (int j = 0; j < 4; j++)
                    acc[r][j] = fma2(zp[r], cp[j], acc[r][j]);
        }

        // epilogue: d = fl( fl(zsq+esq) - 2*dot ); strict-less keeps lowest idx.
        // j ascending visits this thread's codes in increasing order.
        #pragma unroll
        for (int j = 0; j < 4; j++) {
            int cbase = ch * 128 + ((j < 2) ? (c0 + 2 * j) : (64 + c0 + 2 * (j - 2)));
            float e0 = sesq[cbase], e1 = sesq[cbase + 1];
            #pragma unroll
            for (int r = 0; r < 8; r++) {
                float alo, ahi; upk2(acc[r][j], alo, ahi);
                float d0 = __fsub_rn(__fadd_rn(zs[r], e0), __fmul_rn(2.0f, alo));
                if (d0 < bd[r]) { bd[r] = d0; bi[r] = cbase; }
                float d1 = __fsub_rn(__fadd_rn(zs[r], e1), __fmul_rn(2.0f, ahi));
                if (d1 < bd[r]) { bd[r] = d1; bi[r] = cbase + 1; }
            }
        }
    }

    // cross-thread (tx) reduction with lexicographic (d, idx) tie-breaking
    __syncthreads();
    float* rd = scb;                  // 128*16 floats
    int*   ri = (int*)(scb + 2048);   // 128*16 ints
    #pragma unroll
    for (int q = 0; q < 8; q++) {
        rd[(r0 + q) * 16 + tx] = bd[q];
        ri[(r0 + q) * 16 + tx] = bi[q];
    }
    __syncthreads();
    if (tid < TN) {
        float best = rd[tid * 16]; int besti = ri[tid * 16];
        #pragma unroll
        for (int t = 1; t < 16; t++) {
            float dv = rd[tid * 16 + t]; int iv = ri[tid * 16 + t];
            if (dv < best || (dv == best && iv < besti)) { best = dv; besti = iv; }
        }
        swin[tid] = besti;
        outIdx[m * NPOS + n0 + tid] = (float)besti;
        atomicAdd(outBins + besti, 1.0f);   // integer-valued float adds: exact
    }
    __syncthreads();

    // ---- fused gather: stage winning code rows into sq[row][d], stride 65 ----
    float* sq = scb;   // 128*65 = 8320 floats; fits in scb(8192)+sesq(1024)
    const float* cbm = cbk + (size_t)m * N_E * E_DIM;
    #pragma unroll
    for (int it = 0; it < 8; it++) {
        int i = tid + it * 256;          // 0..2047
        int row = i >> 4, d4 = (i & 15) * 4;
        int idx = swin[row];
        float4 v = *(const float4*)(cbm + (size_t)idx * E_DIM + d4);
        float* dp = sq + row * 65 + d4;
        dp[0] = v.x; dp[1] = v.y; dp[2] = v.z; dp[3] = v.w;
    }
    __syncthreads();

    // ---- write z_vq = zf + (zq - zf), accumulate loss partial in double ----
    double lsum = 0.0;
    float* ob = outZvq + ((size_t)(b * CC_ + m * E_DIM)) * HW_ + p0;
    #pragma unroll
    for (int it = 0; it < 8; it++) {
        int i = tid + it * 256;
        int d = i >> 5, j4 = (i & 31) * 4;
        float o[4];
        #pragma unroll
        for (int q = 0; q < 4; q++) {
            float zf = szt[d * 256 + 2 * (j4 + q)];
            float zq = sq[(j4 + q) * 65 + d];
            float df = __fsub_rn(zq, zf);
            o[q] = __fadd_rn(zf, df);
            lsum += (double)df * (double)df;
        }
        *(float4*)(ob + (size_t)d * HW_ + j4) = make_float4(o[0], o[1], o[2], o[3]);
    }

    // deterministic per-block reduction -> g_part[m*128 + blockIdx.x]
    #pragma unroll
    for (int off = 16; off > 0; off >>= 1)
        lsum += __shfl_down_sync(0xffffffffu, lsum, off);
    int lane = tid & 31, wid = tid >> 5;
    if (lane == 0) swarp[wid] = lsum;
    __syncthreads();
    if (wid == 0) {
        double v = (lane < 8) ? swarp[lane] : 0.0;
        #pragma unroll
        for (int off = 4; off > 0; off >>= 1)
            v += __shfl_down_sync(0xffffffffu, v, off);
        if (lane == 0) g_part[m * 128 + blockIdx.x] = v;
    }
}

// ---------------- K3: finalize loss (deterministic fixed-order sum) -----------
__global__ void pq_loss_kernel(float* __restrict__ outLoss) {
    __shared__ double sred[256];
    int t = threadIdx.x;
    double s = 0.0;
    for (int i = t; i < 1024; i += 256) s += g_part[i];
    sred[t] = s;
    __syncthreads();
    for (int off = 128; off > 0; off >>= 1) {
        if (t < off) sred[t] += sred[t + off];
        __syncthreads();
    }
    if (t == 0) {
        double loss = 1.25 * sred[0] / (double)((size_t)NPOS * E_DIM);
        outLoss[0] = (float)loss;
    }
}

// ---------------- launch -------------------------------------------------------
extern "C" void kernel_launch(void* const* d_in, const int* in_sizes, int n_in,
                              void* d_out, int out_size)
{
    const float* z   = (const float*)d_in[0];
    const float* cbk = (const float*)d_in[1];
    if (n_in >= 2 && in_sizes[0] == M_SUB * N_E * E_DIM) {  // swapped-order safety
        z   = (const float*)d_in[1];
        cbk = (const float*)d_in[0];
    }
    float* out = (float*)d_out;
    float* outZvq  = out + OFF_ZVQ;
    float* outLoss = out + OFF_LOSS;
    float* outIdx  = out + OFF_IDX;
    float* outBins = out + OFF_BIN;

    const int dyn_smem = 25856 * 4;   // 103424 B
    cudaFuncSetAttribute(pq_dist_kernel,
                         cudaFuncAttributeMaxDynamicSharedMemorySize, dyn_smem);

    pq_init_kernel<<<1, 1024>>>(outBins);
    pq_esq_kernel<<<(M_SUB * N_E + 255) / 256, 256>>>(cbk);
    pq_tr_kernel<<<64, 256>>>(cbk);
    dim3 g1(NPOS / TN, M_SUB);
    pq_dist_kernel<<<g1, 256, dyn_smem>>>(z, cbk, outZvq, outIdx, outBins);
    pq_loss_kernel<<<1, 256>>>(outLoss);
}

// round 7
// speedup vs baseline: 1.0007x; 1.0007x over previous
#include <cuda_runtime.h>
#include <cstdint>

// Problem constants
#define M_SUB   8
#define N_E     1024
#define E_DIM   64
#define BS_     16
#define CC_     512
#define HW_     1024
#define NPOS    16384            // BS_*HW_

// Output layout (float32)
#define OFF_ZVQ  0
#define OFF_LOSS 8388608
#define OFF_IDX  8388609
#define OFF_BIN  8519681

// Scratch (device globals; no allocation allowed)
__device__ float  g_esq[M_SUB * N_E];
__device__ float  g_cbt[M_SUB * E_DIM * N_E];   // transposed codebooks [m][k][code]
__device__ double g_part[1024];

// ---------------- f32x2 packed FMA helpers -----------------------------------
__device__ __forceinline__ void upk2(unsigned long long v, float& lo, float& hi) {
    asm("mov.b64 {%0, %1}, %2;" : "=f"(lo), "=f"(hi) : "l"(v));
}
__device__ __forceinline__ unsigned long long fma2(unsigned long long a,
                                                   unsigned long long b,
                                                   unsigned long long c) {
    unsigned long long d;
    asm("fma.rn.f32x2 %0, %1, %2, %3;" : "=l"(d) : "l"(a), "l"(b), "l"(c));
    return d;
}

// ---------------- K0: zero bins -----------------------------------------------
__global__ void pq_init_kernel(float* __restrict__ outBins) {
    int t = threadIdx.x;
    if (t < N_E) outBins[t] = 0.0f;
}

// ---------------- K_esq: per-code squared norms (mul then sequential add) -----
__global__ void pq_esq_kernel(const float* __restrict__ cbk) {
    int t = blockIdx.x * blockDim.x + threadIdx.x;   // 0..8191
    if (t >= M_SUB * N_E) return;
    const float* p = cbk + (size_t)t * E_DIM;
    float s = 0.0f;
    #pragma unroll
    for (int d = 0; d < E_DIM; d++) {
        float v = p[d];
        s = __fadd_rn(s, __fmul_rn(v, v));
    }
    g_esq[t] = s;
}

// ---------------- K_tr: transpose codebooks to k-major ------------------------
// grid = 64 blocks (8 m x 8 code-tiles of 128), 256 threads
__global__ void pq_tr_kernel(const float* __restrict__ cbk) {
    __shared__ float st[64 * 128];
    int m  = blockIdx.x >> 3;
    int ct = (blockIdx.x & 7) * 128;
    int tid = threadIdx.x;
    int code = tid >> 1;             // 0..127
    int kh = (tid & 1) * 32;         // 0 or 32
    const float* src = cbk + ((size_t)(m * N_E) + ct + code) * E_DIM + kh;
    #pragma unroll
    for (int q = 0; q < 8; q++) {
        float4 v = *(const float4*)(src + q * 4);
        st[(kh + q * 4 + 0) * 128 + code] = v.x;
        st[(kh + q * 4 + 1) * 128 + code] = v.y;
        st[(kh + q * 4 + 2) * 128 + code] = v.z;
        st[(kh + q * 4 + 3) * 128 + code] = v.w;
    }
    __syncthreads();
    float* dst = g_cbt + (size_t)m * E_DIM * N_E + ct;
    #pragma unroll
    for (int it = 0; it < 8; it++) {
        int i = tid + it * 256;
        int k = i >> 5, c4 = (i & 31) * 4;
        *(float4*)(dst + (size_t)k * N_E + c4) = *(const float4*)(st + k * 128 + c4);
    }
}

// ---------------- K1: distances + argmin + fused z_vq/loss --------------------
// Block 256 threads. Tile: 128 rows x 1024 codes (8 chunks of 128).
// grid = (128 row-tiles, 8 sub-codebooks)
#define TN 128

__global__ void __launch_bounds__(256, 2)
pq_dist_kernel(const float* __restrict__ z,
               const float* __restrict__ cbk,
               float* __restrict__ outZvq,
               float* __restrict__ outIdx,
               float* __restrict__ outBins)
{
    extern __shared__ float sm[];
    float* szt  = sm;                        // 64*256 = 16384 (z tile, duplicated pairs)
    float* scb  = sm + 16384;                // 64*128 = 8192 (codebook chunk, k-major)
    float* sesq = scb + 8192;                // 1024
    float* szsq = sesq + 1024;               // 128
    int*   swin = (int*)(szsq + 128);        // 128
    // total 25856 floats = 103424 B

    __shared__ double swarp[8];

    const int m  = blockIdx.y;
    const int n0 = blockIdx.x * TN;
    const int b  = n0 >> 10;
    const int p0 = n0 & 1023;
    const int tid = threadIdx.x;
    const int tx = tid & 15, ty = tid >> 4;

    // Load z tile (channels [m*64, m*64+64), positions [p0, p0+128)), duplicated:
    // szt[k][2*j] = szt[k][2*j+1] = z[k][j]
    const float* zbase = z + ((size_t)(b * CC_ + m * E_DIM) * HW_) + p0;
    #pragma unroll
    for (int it = 0; it < 8; it++) {
        int i = tid + it * 256;
        int d = i >> 5, j4 = (i & 31) * 4;
        float4 v = *(const float4*)(zbase + (size_t)d * HW_ + j4);
        float* dst = szt + d * 256 + 2 * j4;
        *(float4*)(dst)     = make_float4(v.x, v.x, v.y, v.y);
        *(float4*)(dst + 4) = make_float4(v.z, v.z, v.w, v.w);
    }
    #pragma unroll
    for (int it = 0; it < 4; it++)
        sesq[tid + it * 256] = g_esq[m * N_E + tid + it * 256];
    __syncthreads();

    // per-row ||z||^2: square rounded, then sequential add
    if (tid < TN) {
        float s = 0.0f;
        #pragma unroll
        for (int k = 0; k < E_DIM; k++) {
            float v = szt[k * 256 + 2 * tid];
            s = __fadd_rn(s, __fmul_rn(v, v));
        }
        szsq[tid] = s;
    }
    __syncthreads();

    const int r0 = ty * 8;       // thread's 8 rows
    const int c0 = tx * 4;       // thread's codes: {c0..c0+3, 64+c0..64+c0+3} per chunk
    float zs[8];
    #pragma unroll
    for (int q = 0; q < 8; q++) zs[q] = szsq[r0 + q];

    const float INFF = __int_as_float(0x7f800000);
    float bd[8]; int bi[8];
    #pragma unroll
    for (int q = 0; q < 8; q++) { bd[q] = INFF; bi[q] = 0; }

    const float* ctb = g_cbt + (size_t)m * (E_DIM * N_E);

    for (int ch = 0; ch < 8; ch++) {
        __syncthreads();
        // fill codebook chunk (already k-major in gmem): 2048 float4
        #pragma unroll
        for (int it = 0; it < 8; it++) {
            int i = tid + it * 256;
            int k = i >> 5, c4 = (i & 31) * 4;
            float4 v = *(const float4*)(ctb + (size_t)k * N_E + ch * 128 + c4);
            *(float4*)(scb + k * 128 + c4) = v;
        }
        __syncthreads();

        unsigned long long acc[8][4];
        #pragma unroll
        for (int r = 0; r < 8; r++)
            #pragma unroll
            for (int j = 0; j < 4; j++) acc[r][j] = 0ull;

        #pragma unroll 4
        for (int k = 0; k < E_DIM; k++) {
            const float* zr = szt + k * 256 + 2 * r0;
            ulonglong2 za = *(const ulonglong2*)(zr);        // rows r0,r0+1 dup
            ulonglong2 zb = *(const ulonglong2*)(zr + 4);    // r0+2,r0+3
            ulonglong2 zc = *(const ulonglong2*)(zr + 8);
            ulonglong2 zd = *(const ulonglong2*)(zr + 12);
            const float* cr = scb + k * 128 + c0;
            ulonglong2 ca = *(const ulonglong2*)(cr);        // codes (c0,c0+1),(c0+2,c0+3)
            ulonglong2 cb = *(const ulonglong2*)(cr + 64);   // codes 64+c0 ...
            unsigned long long zp[8] = {za.x, za.y, zb.x, zb.y, zc.x, zc.y, zd.x, zd.y};
            unsigned long long cp[4] = {ca.x, ca.y, cb.x, cb.y};
            #pragma unroll
            for (int r = 0; r < 8; r++)
                #pragma unroll
                for (int j = 0; j < 4; j++)
                    acc[r][j] = fma2(zp[r], cp[j], acc[r][j]);
        }

        // epilogue: d = fl( fl(zsq+esq) - 2*dot ); strict-less keeps lowest idx.
        // j ascending visits this thread's codes in increasing order.
        #pragma unroll
        for (int j = 0; j < 4; j++) {
            int cbase = ch * 128 + ((j < 2) ? (c0 + 2 * j) : (64 + c0 + 2 * (j - 2)));
            float e0 = sesq[cbase], e1 = sesq[cbase + 1];
            #pragma unroll
            for (int r = 0; r < 8; r++) {
                float alo, ahi; upk2(acc[r][j], alo, ahi);
                float d0 = __fsub_rn(__fadd_rn(zs[r], e0), __fmul_rn(2.0f, alo));
                if (d0 < bd[r]) { bd[r] = d0; bi[r] = cbase; }
                float d1 = __fsub_rn(__fadd_rn(zs[r], e1), __fmul_rn(2.0f, ahi));
                if (d1 < bd[r]) { bd[r] = d1; bi[r] = cbase + 1; }
            }
        }
    }

    // cross-thread (tx) reduction with lexicographic (d, idx) tie-breaking
    __syncthreads();
    float* rd = scb;                  // 128*16 floats
    int*   ri = (int*)(scb + 2048);   // 128*16 ints
    #pragma unroll
    for (int q = 0; q < 8; q++) {
        rd[(r0 + q) * 16 + tx] = bd[q];
        ri[(r0 + q) * 16 + tx] = bi[q];
    }
    __syncthreads();
    if (tid < TN) {
        float best = rd[tid * 16]; int besti = ri[tid * 16];
        #pragma unroll
        for (int t = 1; t < 16; t++) {
            float dv = rd[tid * 16 + t]; int iv = ri[tid * 16 + t];
            if (dv < best || (dv == best && iv < besti)) { best = dv; besti = iv; }
        }
        swin[tid] = besti;
        outIdx[m * NPOS + n0 + tid] = (float)besti;
        atomicAdd(outBins + besti, 1.0f);   // integer-valued float adds: exact
    }
    __syncthreads();

    // ---- fused gather: stage winning code rows into sq[row][d], stride 65 ----
    float* sq = scb;   // 128*65 = 8320 floats; fits in scb(8192)+sesq(1024)
    const float* cbm = cbk + (size_t)m * N_E * E_DIM;
    #pragma unroll
    for (int it = 0; it < 8; it++) {
        int i = tid + it * 256;          // 0..2047
        int row = i >> 4, d4 = (i & 15) * 4;
        int idx = swin[row];
        float4 v = *(const float4*)(cbm + (size_t)idx * E_DIM + d4);
        float* dp = sq + row * 65 + d4;
        dp[0] = v.x; dp[1] = v.y; dp[2] = v.z; dp[3] = v.w;
    }
    __syncthreads();

    // ---- write z_vq = zf + (zq - zf), accumulate loss partial in double ----
    double lsum = 0.0;
    float* ob = outZvq + ((size_t)(b * CC_ + m * E_DIM)) * HW_ + p0;
    #pragma unroll
    for (int it = 0; it < 8; it++) {
        int i = tid + it * 256;
        int d = i >> 5, j4 = (i & 31) * 4;
        float o[4];
        #pragma unroll
        for (int q = 0; q < 4; q++) {
            float zf = szt[d * 256 + 2 * (j4 + q)];
            float zq = sq[(j4 + q) * 65 + d];
            float df = __fsub_rn(zq, zf);
            o[q] = __fadd_rn(zf, df);
            lsum += (double)df * (double)df;
        }
        *(float4*)(ob + (size_t)d * HW_ + j4) = make_float4(o[0], o[1], o[2], o[3]);
    }

    // deterministic per-block reduction -> g_part[m*128 + blockIdx.x]
    #pragma unroll
    for (int off = 16; off > 0; off >>= 1)
        lsum += __shfl_down_sync(0xffffffffu, lsum, off);
    int lane = tid & 31, wid = tid >> 5;
    if (lane == 0) swarp[wid] = lsum;
    __syncthreads();
    if (wid == 0) {
        double v = (lane < 8) ? swarp[lane] : 0.0;
        #pragma unroll
        for (int off = 4; off > 0; off >>= 1)
            v += __shfl_down_sync(0xffffffffu, v, off);
        if (lane == 0) g_part[m * 128 + blockIdx.x] = v;
    }
}

// ---------------- K3: finalize loss (deterministic fixed-order sum) -----------
__global__ void pq_loss_kernel(float* __restrict__ outLoss) {
    __shared__ double sred[256];
    int t = threadIdx.x;
    double s = 0.0;
    for (int i = t; i < 1024; i += 256) s += g_part[i];
    sred[t] = s;
    __syncthreads();
    for (int off = 128; off > 0; off >>= 1) {
        if (t < off) sred[t] += sred[t + off];
        __syncthreads();
    }
    if (t == 0) {
        double loss = 1.25 * sred[0] / (double)((size_t)NPOS * E_DIM);
        outLoss[0] = (float)loss;
    }
}

// ---------------- launch -------------------------------------------------------
extern "C" void kernel_launch(void* const* d_in, const int* in_sizes, int n_in,
                              void* d_out, int out_size)
{
    const float* z   = (const float*)d_in[0];
    const float* cbk = (const float*)d_in[1];
    if (n_in >= 2 && in_sizes[0] == M_SUB * N_E * E_DIM) {  // swapped-order safety
        z   = (const float*)d_in[1];
        cbk = (const float*)d_in[0];
    }
    float* out = (float*)d_out;
    float* outZvq  = out + OFF_ZVQ;
    float* outLoss = out + OFF_LOSS;
    float* outIdx  = out + OFF_IDX;
    float* outBins = out + OFF_BIN;

    const int dyn_smem = 25856 * 4;   // 103424 B
    cudaFuncSetAttribute(pq_dist_kernel,
                         cudaFuncAttributeMaxDynamicSharedMemorySize, dyn_smem);

    pq_init_kernel<<<1, 1024>>>(outBins);
    pq_esq_kernel<<<(M_SUB * N_E + 255) / 256, 256>>>(cbk);
    pq_tr_kernel<<<64, 256>>>(cbk);
    dim3 g1(NPOS / TN, M_SUB);
    pq_dist_kernel<<<g1, 256, dyn_smem>>>(z, cbk, outZvq, outIdx, outBins);
    pq_loss_kernel<<<1, 256>>>(outLoss);
}

// round 8
// speedup vs baseline: 1.6252x; 1.6240x over previous
#include <cuda_runtime.h>
#include <cstdint>

// Problem constants
#define M_SUB   8
#define N_E     1024
#define E_DIM   64
#define BS_     16
#define CC_     512
#define HW_     1024
#define NPOS    16384            // BS_*HW_

// Output layout (float32)
#define OFF_ZVQ  0
#define OFF_LOSS 8388608
#define OFF_IDX  8388609
#define OFF_BIN  8519681

#define CAP   32        // candidate cap per row
#define EPSF  2e-3f     // collect threshold (>= 3x worst-case tf32 error bound)

// Scratch (device globals; no allocation allowed)
__device__ float  g_esq[M_SUB * N_E];
__device__ float  g_cbt[M_SUB * E_DIM * N_E];   // transposed codebooks [m][k][code]
__device__ double g_part[1024];

// ---------------- helpers ------------------------------------------------------
__device__ __forceinline__ unsigned fkey(float f) {          // order-preserving uint
    unsigned u = __float_as_uint(f);
    return (u & 0x80000000u) ? ~u : (u | 0x80000000u);
}
__device__ __forceinline__ float funkey(unsigned k) {
    return __uint_as_float((k & 0x80000000u) ? (k & 0x7fffffffu) : ~k);
}

__device__ __forceinline__ void mma_tf32(float& d0, float& d1, float& d2, float& d3,
                                         unsigned a0, unsigned a1, unsigned a2, unsigned a3,
                                         unsigned b0, unsigned b1) {
    asm volatile("mma.sync.aligned.m16n8k8.row.col.f32.tf32.tf32.f32 "
                 "{%0,%1,%2,%3}, {%4,%5,%6,%7}, {%8,%9}, {%0,%1,%2,%3};"
                 : "+f"(d0), "+f"(d1), "+f"(d2), "+f"(d3)
                 : "r"(a0), "r"(a1), "r"(a2), "r"(a3), "r"(b0), "r"(b1));
}

// ---------------- K0: zero bins -------------------------------------------------
__global__ void pq_init_kernel(float* __restrict__ outBins) {
    int t = threadIdx.x;
    if (t < N_E) outBins[t] = 0.0f;
}

// ---------------- K_esq: per-code squared norms (mul then sequential add) -------
__global__ void pq_esq_kernel(const float* __restrict__ cbk) {
    int t = blockIdx.x * blockDim.x + threadIdx.x;
    if (t >= M_SUB * N_E) return;
    const float* p = cbk + (size_t)t * E_DIM;
    float s = 0.0f;
    #pragma unroll
    for (int d = 0; d < E_DIM; d++) {
        float v = p[d];
        s = __fadd_rn(s, __fmul_rn(v, v));
    }
    g_esq[t] = s;
}

// ---------------- K_tr: transpose codebooks to k-major --------------------------
__global__ void pq_tr_kernel(const float* __restrict__ cbk) {
    __shared__ float st[64 * 128];
    int m  = blockIdx.x >> 3;
    int ct = (blockIdx.x & 7) * 128;
    int tid = threadIdx.x;
    int code = tid >> 1;
    int kh = (tid & 1) * 32;
    const float* src = cbk + ((size_t)(m * N_E) + ct + code) * E_DIM + kh;
    #pragma unroll
    for (int q = 0; q < 8; q++) {
        float4 v = *(const float4*)(src + q * 4);
        st[(kh + q * 4 + 0) * 128 + code] = v.x;
        st[(kh + q * 4 + 1) * 128 + code] = v.y;
        st[(kh + q * 4 + 2) * 128 + code] = v.z;
        st[(kh + q * 4 + 3) * 128 + code] = v.w;
    }
    __syncthreads();
    float* dst = g_cbt + (size_t)m * E_DIM * N_E + ct;
    #pragma unroll
    for (int it = 0; it < 8; it++) {
        int i = tid + it * 256;
        int k = i >> 5, c4 = (i & 31) * 4;
        *(float4*)(dst + (size_t)k * N_E + c4) = *(const float4*)(st + k * 128 + c4);
    }
}

// ---------------- K1: tf32 MMA scoring + exact rescore + fused epilogue ---------
// Block 256 threads (8 warps). Tile: 128 rows x 1024 codes. grid = (128, 8).
// smem carve (floats):
#define S_ZT    0            // z tile [128][73]           (9344)
#define S_CB    9344         // codebook chunk [64][72]    (4608)
#define S_CAND  13952        // candidates [128][CAP] int  (4096)
#define S_ESQ   18048        // esq                        (1024)
#define S_ZSQ   19072        // zsq                        (128)
#define S_CNT   19200        // counters int               (128)
#define S_RMIN  19328        // row min keys uint          (128)
#define S_WIN   19456        // winners int                (128)
#define S_RBD   19584        // rescore partial d          (256)
#define S_RBI   19840        // rescore partial idx int    (256)
#define S_TOT   20096        // 80384 bytes
#define S_SQ    9344         // gather overlay (needs 8320 <= 4608+4096)

__global__ void __launch_bounds__(256, 2)
pq_dist_kernel(const float* __restrict__ z,
               const float* __restrict__ cbk,
               float* __restrict__ outZvq,
               float* __restrict__ outIdx,
               float* __restrict__ outBins)
{
    extern __shared__ float sm[];
    float*    szt  = sm + S_ZT;
    float*    scb  = sm + S_CB;
    int*      scand= (int*)(sm + S_CAND);
    float*    sesq = sm + S_ESQ;
    float*    szsq = sm + S_ZSQ;
    int*      scnt = (int*)(sm + S_CNT);
    unsigned* srmin= (unsigned*)(sm + S_RMIN);
    int*      swin = (int*)(sm + S_WIN);
    float*    rbd  = sm + S_RBD;
    int*      rbi  = (int*)(sm + S_RBI);
    __shared__ double swarp[8];

    const int m  = blockIdx.y;
    const int n0 = blockIdx.x * 128;
    const int b  = n0 >> 10;
    const int p0 = n0 & 1023;
    const int tid  = threadIdx.x;
    const int wid  = tid >> 5;
    const int lane = tid & 31;
    const int gg   = lane >> 2;      // group id 0..7
    const int lx   = lane & 3;       // thread-in-group
    const int row0 = wid * 16 + gg;  // rows owned by this thread's D frags
    const float INFF = __int_as_float(0x7f800000);

    // ---- load z tile [pos][d] (transpose from gmem [d][pos]) ----
    const float* zbase = z + ((size_t)(b * CC_ + m * E_DIM) * HW_) + p0;
    #pragma unroll
    for (int it = 0; it < 8; it++) {
        int i = tid + it * 256;
        int d = i >> 5, j4 = (i & 31) * 4;
        float4 v = *(const float4*)(zbase + (size_t)d * HW_ + j4);
        szt[(j4 + 0) * 73 + d] = v.x;
        szt[(j4 + 1) * 73 + d] = v.y;
        szt[(j4 + 2) * 73 + d] = v.z;
        szt[(j4 + 3) * 73 + d] = v.w;
    }
    #pragma unroll
    for (int it = 0; it < 4; it++)
        sesq[tid + it * 256] = g_esq[m * N_E + tid + it * 256];
    if (tid < 128) { scnt[tid] = 0; srmin[tid] = 0xffffffffu; }
    __syncthreads();

    // ---- per-row ||z||^2 (sequential chain, matches reference) ----
    if (tid < 128) {
        float s = 0.0f;
        const float* zr = szt + tid * 73;
        #pragma unroll
        for (int k = 0; k < E_DIM; k++)
            s = __fadd_rn(s, __fmul_rn(zr[k], zr[k]));
        szsq[tid] = s;
    }

    // ---- A fragments (held in regs for whole kernel): rows row0/row0+8, k=64 ----
    unsigned afr[8][4];
    {
        const float* za = szt + row0 * 73 + lx;
        const float* zb = szt + (row0 + 8) * 73 + lx;
        #pragma unroll
        for (int ks = 0; ks < 8; ks++) {
            afr[ks][0] = __float_as_uint(za[8 * ks]);
            afr[ks][1] = __float_as_uint(zb[8 * ks]);
            afr[ks][2] = __float_as_uint(za[8 * ks + 4]);
            afr[ks][3] = __float_as_uint(zb[8 * ks + 4]);
        }
    }

    // ---- 16 chunks of 64 codes: MMA -> scores -> running min -> collect ----
    const float* ctb = g_cbt + (size_t)m * (E_DIM * N_E);
    for (int ch = 0; ch < 16; ch++) {
        __syncthreads();   // prev chunk fully consumed
        #pragma unroll
        for (int it = 0; it < 4; it++) {
            int i = tid + it * 256;
            int k = i >> 4, n4 = (i & 15) * 4;
            float4 v = *(const float4*)(ctb + (size_t)k * N_E + ch * 64 + n4);
            *(float4*)(scb + k * 72 + n4) = v;
        }
        __syncthreads();   // chunk ready

        float acc[8][4];
        #pragma unroll
        for (int nt = 0; nt < 8; nt++)
            #pragma unroll
            for (int q = 0; q < 4; q++) acc[nt][q] = 0.0f;

        const float* bp = scb + lx * 72 + gg;
        #pragma unroll
        for (int ks = 0; ks < 8; ks++) {
            #pragma unroll
            for (int nt = 0; nt < 8; nt++) {
                unsigned b0 = __float_as_uint(bp[ks * 576 + nt * 8]);
                unsigned b1 = __float_as_uint(bp[ks * 576 + 288 + nt * 8]);
                mma_tf32(acc[nt][0], acc[nt][1], acc[nt][2], acc[nt][3],
                         afr[ks][0], afr[ks][1], afr[ks][2], afr[ks][3], b0, b1);
            }
        }

        // scores: esq[c] - 2*dot ; running min per row
        float m0 = INFF, m1 = INFF;
        #pragma unroll
        for (int nt = 0; nt < 8; nt++) {
            int c = ch * 64 + nt * 8 + 2 * lx;
            float2 e = *(const float2*)(sesq + c);
            float s0 = __fmaf_rn(acc[nt][0], -2.0f, e.x);
            float s1 = __fmaf_rn(acc[nt][1], -2.0f, e.y);
            float s2 = __fmaf_rn(acc[nt][2], -2.0f, e.x);
            float s3 = __fmaf_rn(acc[nt][3], -2.0f, e.y);
            m0 = fminf(m0, fminf(s0, s1));
            m1 = fminf(m1, fminf(s2, s3));
        }
        #pragma unroll
        for (int off = 1; off <= 2; off <<= 1) {
            m0 = fminf(m0, __shfl_xor_sync(0xffffffffu, m0, off));
            m1 = fminf(m1, __shfl_xor_sync(0xffffffffu, m1, off));
        }
        if (lx == 0) {
            atomicMin(srmin + row0, fkey(m0));
            atomicMin(srmin + row0 + 8, fkey(m1));
        }
        __syncthreads();   // row minima include this chunk

        float thr0 = funkey(srmin[row0]) + EPSF;
        float thr1 = funkey(srmin[row0 + 8]) + EPSF;
        #pragma unroll
        for (int nt = 0; nt < 8; nt++) {
            int c = ch * 64 + nt * 8 + 2 * lx;
            float2 e = *(const float2*)(sesq + c);
            float s0 = __fmaf_rn(acc[nt][0], -2.0f, e.x);
            float s1 = __fmaf_rn(acc[nt][1], -2.0f, e.y);
            float s2 = __fmaf_rn(acc[nt][2], -2.0f, e.x);
            float s3 = __fmaf_rn(acc[nt][3], -2.0f, e.y);
            if (s0 <= thr0) { int p = atomicAdd(scnt + row0, 1);     if (p < CAP) scand[row0 * CAP + p] = c; }
            if (s1 <= thr0) { int p = atomicAdd(scnt + row0, 1);     if (p < CAP) scand[row0 * CAP + p] = c + 1; }
            if (s2 <= thr1) { int p = atomicAdd(scnt + row0 + 8, 1); if (p < CAP) scand[(row0 + 8) * CAP + p] = c; }
            if (s3 <= thr1) { int p = atomicAdd(scnt + row0 + 8, 1); if (p < CAP) scand[(row0 + 8) * CAP + p] = c + 1; }
        }
    }
    __syncthreads();

    // ---- exact rescore (reference-identical fp32 chains); 2 threads per row ----
    {
        int row = (tid < 128) ? tid : tid - 128;
        int start = (tid < 128) ? 0 : 1;
        int cnt = scnt[row];
        const float* zr = szt + row * 73;
        float zsqv = szsq[row];
        const float* cbm = cbk + (size_t)m * N_E * E_DIM;
        float bd = INFF; int bi = 0x7fffffff;

        auto exact_d = [&](int c) -> float {
            const float* cr = cbm + (size_t)c * E_DIM;
            float s = 0.0f;
            #pragma unroll
            for (int g4 = 0; g4 < 4; g4++) {
                float4 c0 = *(const float4*)(cr + g4 * 16);
                float4 c1 = *(const float4*)(cr + g4 * 16 + 4);
                float4 c2 = *(const float4*)(cr + g4 * 16 + 8);
                float4 c3 = *(const float4*)(cr + g4 * 16 + 12);
                const float* zp = zr + g4 * 16;
                s = __fmaf_rn(zp[0],  c0.x, s); s = __fmaf_rn(zp[1],  c0.y, s);
                s = __fmaf_rn(zp[2],  c0.z, s); s = __fmaf_rn(zp[3],  c0.w, s);
                s = __fmaf_rn(zp[4],  c1.x, s); s = __fmaf_rn(zp[5],  c1.y, s);
                s = __fmaf_rn(zp[6],  c1.z, s); s = __fmaf_rn(zp[7],  c1.w, s);
                s = __fmaf_rn(zp[8],  c2.x, s); s = __fmaf_rn(zp[9],  c2.y, s);
                s = __fmaf_rn(zp[10], c2.z, s); s = __fmaf_rn(zp[11], c2.w, s);
                s = __fmaf_rn(zp[12], c3.x, s); s = __fmaf_rn(zp[13], c3.y, s);
                s = __fmaf_rn(zp[14], c3.z, s); s = __fmaf_rn(zp[15], c3.w, s);
            }
            return __fsub_rn(__fadd_rn(zsqv, sesq[c]), __fmul_rn(2.0f, s));
        };

        if (cnt <= CAP) {
            for (int i = start; i < cnt; i += 2) {
                int c = scand[row * CAP + i];
                float d = exact_d(c);
                if (d < bd || (d == bd && c < bi)) { bd = d; bi = c; }
            }
        } else {  // overflow fallback: full exact scan (provably correct, ~never)
            for (int c = start; c < N_E; c += 2) {
                float d = exact_d(c);
                if (d < bd || (d == bd && c < bi)) { bd = d; bi = c; }
            }
        }
        rbd[tid] = bd; rbi[tid] = bi;
    }
    __syncthreads();
    if (tid < 128) {
        float bd = rbd[tid]; int bi = rbi[tid];
        float d2 = rbd[tid + 128]; int i2 = rbi[tid + 128];
        if (d2 < bd || (d2 == bd && i2 < bi)) { bd = d2; bi = i2; }
        swin[tid] = bi;
        outIdx[m * NPOS + n0 + tid] = (float)bi;
        atomicAdd(outBins + bi, 1.0f);   // integer-valued float adds: exact
    }
    __syncthreads();

    // ---- gather winning code rows into sq[row][d], stride 65 (overlay) ----
    float* sq = sm + S_SQ;
    const float* cbm = cbk + (size_t)m * N_E * E_DIM;
    #pragma unroll
    for (int it = 0; it < 8; it++) {
        int i = tid + it * 256;
        int row = i >> 4, d4 = (i & 15) * 4;
        int idx = swin[row];
        float4 v = *(const float4*)(cbm + (size_t)idx * E_DIM + d4);
        float* dp = sq + row * 65 + d4;
        dp[0] = v.x; dp[1] = v.y; dp[2] = v.z; dp[3] = v.w;
    }
    __syncthreads();

    // ---- z_vq = zf + (zq - zf); loss partial in double ----
    double lsum = 0.0;
    float* ob = outZvq + ((size_t)(b * CC_ + m * E_DIM)) * HW_ + p0;
    #pragma unroll
    for (int it = 0; it < 8; it++) {
        int i = tid + it * 256;
        int d = i >> 5, j4 = (i & 31) * 4;
        float o[4];
        #pragma unroll
        for (int q = 0; q < 4; q++) {
            float zf = szt[(j4 + q) * 73 + d];
            float zq = sq[(j4 + q) * 65 + d];
            float df = __fsub_rn(zq, zf);
            o[q] = __fadd_rn(zf, df);
            lsum += (double)df * (double)df;
        }
        *(float4*)(ob + (size_t)d * HW_ + j4) = make_float4(o[0], o[1], o[2], o[3]);
    }

    #pragma unroll
    for (int off = 16; off > 0; off >>= 1)
        lsum += __shfl_down_sync(0xffffffffu, lsum, off);
    if (lane == 0) swarp[wid] = lsum;
    __syncthreads();
    if (wid == 0) {
        double v = (lane < 8) ? swarp[lane] : 0.0;
        #pragma unroll
        for (int off = 4; off > 0; off >>= 1)
            v += __shfl_down_sync(0xffffffffu, v, off);
        if (lane == 0) g_part[m * 128 + blockIdx.x] = v;
    }
}

// ---------------- K3: finalize loss ---------------------------------------------
__global__ void pq_loss_kernel(float* __restrict__ outLoss) {
    __shared__ double sred[256];
    int t = threadIdx.x;
    double s = 0.0;
    for (int i = t; i < 1024; i += 256) s += g_part[i];
    sred[t] = s;
    __syncthreads();
    for (int off = 128; off > 0; off >>= 1) {
        if (t < off) sred[t] += sred[t + off];
        __syncthreads();
    }
    if (t == 0) {
        double loss = 1.25 * sred[0] / (double)((size_t)NPOS * E_DIM);
        outLoss[0] = (float)loss;
    }
}

// ---------------- launch ----------------------------------------------------------
extern "C" void kernel_launch(void* const* d_in, const int* in_sizes, int n_in,
                              void* d_out, int out_size)
{
    const float* z   = (const float*)d_in[0];
    const float* cbk = (const float*)d_in[1];
    if (n_in >= 2 && in_sizes[0] == M_SUB * N_E * E_DIM) {  // swapped-order safety
        z   = (const float*)d_in[1];
        cbk = (const float*)d_in[0];
    }
    float* out = (float*)d_out;
    float* outZvq  = out + OFF_ZVQ;
    float* outLoss = out + OFF_LOSS;
    float* outIdx  = out + OFF_IDX;
    float* outBins = out + OFF_BIN;

    const int dyn_smem = S_TOT * 4;   // 80384 B
    cudaFuncSetAttribute(pq_dist_kernel,
                         cudaFuncAttributeMaxDynamicSharedMemorySize, dyn_smem);

    pq_init_kernel<<<1, 1024>>>(outBins);
    pq_esq_kernel<<<(M_SUB * N_E + 255) / 256, 256>>>(cbk);
    pq_tr_kernel<<<64, 256>>>(cbk);
    dim3 g1(NPOS / 128, M_SUB);
    pq_dist_kernel<<<g1, 256, dyn_smem>>>(z, cbk, outZvq, outIdx, outBins);
    pq_loss_kernel<<<1, 256>>>(outLoss);
}